// round 13
// baseline (speedup 1.0000x reference)
#include <cuda_runtime.h>

#define HW  (512 * 512)
#define HW4 (HW / 4)

// Hue/sat adjust for one pixel, in h6 = hue*6 space.
//
// Derivation notes (vs the jax reference):
//  - rgb2hsv hsum matches the reference's hr/hg/hb priority chain exactly.
//  - h6 = mod(hsum + 6*dh, 6) folds reference's  mod(hsum,6)/6, +dh, mod(.,1), *6
//    into a single wrap (identical mod 6).
//  - hsv2rgb via trapezoid: chan(n) = v - v*s*clamp(min(k, 4-k), 0, 1) with
//    k = wrap6(h6+n), n = 5/3/1 for R/G/B — reproduces the v,q,p,p,t,v sector
//    table exactly, including the h6==6.0 edge (maps to sector-0 values).
//  - reference's clips on p/q/t are no-ops here since results lie in [0, v].
__device__ __forceinline__ void adjust_px(float r, float g, float b,
                                          float dh6, float ds,
                                          float& ro, float& go, float& bo) {
    float maxc = fmaxf(r, fmaxf(g, b));
    float minc = fminf(r, fminf(g, b));
    float cr   = maxc - minc;
    bool  eq   = (cr == 0.0f);

    float s   = __fdividef(cr, eq ? 1.0f : maxc);
    float inv = __fdividef(1.0f, eq ? 1.0f : cr);
    float rc = (maxc - r) * inv;
    float gc = (maxc - g) * inv;
    float bc = (maxc - b) * inv;

    float hsum = (maxc == r) ? (bc - gc)
               : (maxc == g) ? (2.0f + rc - bc)
                             : (4.0f + gc - rc);

    // h6 = mod(hsum + 6*dh, 6)
    float x  = hsum + dh6;
    float h6 = fmaf(-6.0f, floorf(x * (1.0f / 6.0f)), x);

    float sadj = __saturatef(s * ds);
    float v    = maxc;
    float vs   = v * sadj;

    // channel(n): k = wrap6(h6+n); m = clamp(min(k, 4-k), 0, 1); v - vs*m
    {
        float k = h6 + 5.0f;
        k = (k >= 6.0f) ? k - 6.0f : k;
        float m = fmaxf(fminf(fminf(k, 4.0f - k), 1.0f), 0.0f);
        ro = fmaf(-vs, m, v);
    }
    {
        float k = h6 + 3.0f;
        k = (k >= 6.0f) ? k - 6.0f : k;
        float m = fmaxf(fminf(fminf(k, 4.0f - k), 1.0f), 0.0f);
        go = fmaf(-vs, m, v);
    }
    {
        float k = h6 + 1.0f;
        k = (k >= 6.0f) ? k - 6.0f : k;
        float m = fmaxf(fminf(fminf(k, 4.0f - k), 1.0f), 0.0f);
        bo = fmaf(-vs, m, v);
    }
}

__global__ __launch_bounds__(512, 4)
void adjust_hue_sat_kernel(const float* __restrict__ imgs,
                           const float* __restrict__ xform,
                           float* __restrict__ out) {
    int batch = blockIdx.y;
    int idx   = blockIdx.x * 512 + threadIdx.x;      // [0, HW4)

    float dh6 = 6.0f * __ldg(&xform[2 * batch]);
    float ds  = __ldg(&xform[2 * batch + 1]);

    const float4* base = (const float4*)(imgs + (size_t)batch * 3 * HW);

    // Streaming loads/stores: data touched exactly once.
    float4 r4 = __ldcs(base + idx);
    float4 g4 = __ldcs(base + idx + HW4);
    float4 b4 = __ldcs(base + idx + 2 * HW4);

    float4 ro4, go4, bo4;
    adjust_px(r4.x, g4.x, b4.x, dh6, ds, ro4.x, go4.x, bo4.x);
    adjust_px(r4.y, g4.y, b4.y, dh6, ds, ro4.y, go4.y, bo4.y);
    adjust_px(r4.z, g4.z, b4.z, dh6, ds, ro4.z, go4.z, bo4.z);
    adjust_px(r4.w, g4.w, b4.w, dh6, ds, ro4.w, go4.w, bo4.w);

    float4* obase = (float4*)(out + (size_t)batch * 3 * HW);
    __stcs(obase + idx,           ro4);
    __stcs(obase + idx + HW4,     go4);
    __stcs(obase + idx + 2 * HW4, bo4);
}

extern "C" void kernel_launch(void* const* d_in, const int* in_sizes, int n_in,
                              void* d_out, int out_size) {
    const float* imgs  = (const float*)d_in[0];
    const float* xform = (const float*)d_in[1];
    float*       out   = (float*)d_out;

    dim3 block(512);
    dim3 grid(HW4 / 512, 64);    // 128 x 64 blocks, 4 px per thread
    adjust_hue_sat_kernel<<<grid, block>>>(imgs, xform, out);
}

// round 14
// speedup vs baseline: 1.0258x; 1.0258x over previous
#include <cuda_runtime.h>

#define HW  (512 * 512)
#define HW4 (HW / 4)

// Hue/sat adjust for one pixel, in h6 = hue*6 space.
//
// Derivation notes (vs the jax reference):
//  - rgb2hsv hsum matches the reference's hr/hg/hb priority chain exactly.
//  - h6 = mod(hsum + 6*dh, 6) folds reference's  mod(hsum,6)/6, +dh, mod(.,1), *6
//    into a single wrap (identical mod 6).
//  - hsv2rgb via trapezoid: chan(n) = v - v*s*clamp(min(k, 4-k), 0, 1) with
//    k = wrap6(h6+n), n = 5/3/1 for R/G/B — reproduces the v,q,p,p,t,v sector
//    table exactly, including the h6==6.0 edge (maps to sector-0 values).
//  - reference's clips on p/q/t are no-ops here since results lie in [0, v].
__device__ __forceinline__ void adjust_px(float r, float g, float b,
                                          float dh6, float ds,
                                          float& ro, float& go, float& bo) {
    float maxc = fmaxf(r, fmaxf(g, b));
    float minc = fminf(r, fminf(g, b));
    float cr   = maxc - minc;
    bool  eq   = (cr == 0.0f);

    float s   = __fdividef(cr, eq ? 1.0f : maxc);
    float inv = __fdividef(1.0f, eq ? 1.0f : cr);
    float rc = (maxc - r) * inv;
    float gc = (maxc - g) * inv;
    float bc = (maxc - b) * inv;

    float hsum = (maxc == r) ? (bc - gc)
               : (maxc == g) ? (2.0f + rc - bc)
                             : (4.0f + gc - rc);

    // h6 = mod(hsum + 6*dh, 6)
    float x  = hsum + dh6;
    float h6 = fmaf(-6.0f, floorf(x * (1.0f / 6.0f)), x);

    float sadj = __saturatef(s * ds);
    float v    = maxc;
    float vs   = v * sadj;

    // channel(n): k = wrap6(h6+n); m = clamp(min(k, 4-k), 0, 1); v - vs*m
    {
        float k = h6 + 5.0f;
        k = (k >= 6.0f) ? k - 6.0f : k;
        float m = fmaxf(fminf(fminf(k, 4.0f - k), 1.0f), 0.0f);
        ro = fmaf(-vs, m, v);
    }
    {
        float k = h6 + 3.0f;
        k = (k >= 6.0f) ? k - 6.0f : k;
        float m = fmaxf(fminf(fminf(k, 4.0f - k), 1.0f), 0.0f);
        go = fmaf(-vs, m, v);
    }
    {
        float k = h6 + 1.0f;
        k = (k >= 6.0f) ? k - 6.0f : k;
        float m = fmaxf(fminf(fminf(k, 4.0f - k), 1.0f), 0.0f);
        bo = fmaf(-vs, m, v);
    }
}

__global__ __launch_bounds__(512, 4)
void adjust_hue_sat_kernel(const float* __restrict__ imgs,
                           const float* __restrict__ xform,
                           float* __restrict__ out) {
    int batch = blockIdx.y;
    int idx   = blockIdx.x * 512 + threadIdx.x;      // [0, HW4)

    float dh6 = 6.0f * __ldg(&xform[2 * batch]);
    float ds  = __ldg(&xform[2 * batch + 1]);

    const float4* base = (const float4*)(imgs + (size_t)batch * 3 * HW);

    // Streaming loads/stores: data touched exactly once.
    float4 r4 = __ldcs(base + idx);
    float4 g4 = __ldcs(base + idx + HW4);
    float4 b4 = __ldcs(base + idx + 2 * HW4);

    float4 ro4, go4, bo4;
    adjust_px(r4.x, g4.x, b4.x, dh6, ds, ro4.x, go4.x, bo4.x);
    adjust_px(r4.y, g4.y, b4.y, dh6, ds, ro4.y, go4.y, bo4.y);
    adjust_px(r4.z, g4.z, b4.z, dh6, ds, ro4.z, go4.z, bo4.z);
    adjust_px(r4.w, g4.w, b4.w, dh6, ds, ro4.w, go4.w, bo4.w);

    float4* obase = (float4*)(out + (size_t)batch * 3 * HW);
    __stcs(obase + idx,           ro4);
    __stcs(obase + idx + HW4,     go4);
    __stcs(obase + idx + 2 * HW4, bo4);
}

extern "C" void kernel_launch(void* const* d_in, const int* in_sizes, int n_in,
                              void* d_out, int out_size) {
    const float* imgs  = (const float*)d_in[0];
    const float* xform = (const float*)d_in[1];
    float*       out   = (float*)d_out;

    dim3 block(512);
    dim3 grid(HW4 / 512, 64);    // 128 x 64 blocks, 4 px per thread
    adjust_hue_sat_kernel<<<grid, block>>>(imgs, xform, out);
}